// round 14
// baseline (speedup 1.0000x reference)
#include <cuda_runtime.h>
#include <cuda_bf16.h>

// out[m, r, t] = X0[r] + t * fl(dt * dXdt[r]),  m=0 -> S, m=1 -> I
// Closed form matches jax associative_scan cumsum to ~2e-7 (verified R2-R8).
//
// R10: single kernel node (multi-node graphs charge ~2us/node, R5/R7).
// Prologue cost (~0.6us, R5-vs-R8 diff) attacked via: float4 prologue
// loads (12 LDG vs 31), 806 CTAs instead of 1066 (VPT 16), and a single
// I2F per thread (remaining time indices are exact float adds).

#define NROWS 13

static constexpr int THREADS = 256;
static constexpr int VPT     = 16;                  // float4s per thread
static constexpr int EPB     = THREADS * VPT * 4;   // 16384 elems per CTA

__global__ void __launch_bounds__(THREADS)
sei_fill_kernel(const float* __restrict__ S0,
                const float* __restrict__ E0,
                const float* __restrict__ I0,
                const float* __restrict__ L,
                const float* __restrict__ beta_p,
                const float* __restrict__ gamma_p,
                const float* __restrict__ K_p,
                const float* __restrict__ Ki_p,
                const float* __restrict__ dt_p,
                float* __restrict__ out,
                int nt)
{
    const int y = blockIdx.y;                      // row index: m*13 + r
    const int m = (y >= NROWS) ? 1 : 0;
    const int r = y - m * NROWS;

    // Barrier-free prologue, vectorized loads. All threads compute the same
    // (step, x0); loads are CTA-uniform (broadcast), L1-hit after first CTAs.
    float step, x0;
    {
        // State vector for this half: S0 (m=0) or I0 (m=1).
        const float* __restrict__ X = (m == 0) ? S0 : I0;

        // Load X[0..12] with 3x float4 + 1 scalar.
        float xv[16];
        {
            const float4 a = __ldg((const float4*)(X + 0));
            const float4 b = __ldg((const float4*)(X + 4));
            const float4 c = __ldg((const float4*)(X + 8));
            xv[0]=a.x; xv[1]=a.y; xv[2]=a.z;  xv[3]=b.x-b.x+a.w;
            xv[3]=a.w; xv[4]=b.x; xv[5]=b.y;  xv[6]=b.z; xv[7]=b.w;
            xv[8]=c.x; xv[9]=c.y; xv[10]=c.z; xv[11]=c.w;
            xv[12] = __ldg(X + 12);
        }

        // L row: 13 floats starting at r*13 (unaligned in general) -> scalar
        // loads but issued back-to-back (independent, one latency round).
        float lv[NROWS];
        #pragma unroll
        for (int c = 0; c < NROWS; ++c) lv[c] = __ldg(L + r * NROWS + c);

        float acc = 0.0f;
        #pragma unroll
        for (int c = 0; c < NROWS; ++c) acc = fmaf(lv[c], xv[c], acc);

        const float h = __ldg(dt_p);
        if (m == 0) {
            const float s0r = xv[r <= 12 ? r : 0];  // xv holds S0; r in [0,13)
            const float dS = -__ldg(K_p) * acc
                             - __ldg(beta_p)  * __ldg(E0 + r) * s0r
                             - __ldg(gamma_p) * __ldg(I0 + r) * s0r;
            step = h * dS;
            x0   = s0r;
        } else {
            const float i0r = xv[r <= 12 ? r : 0];  // xv holds I0
            const float dI = -__ldg(Ki_p) * acc
                             + 0.2f  * __ldg(E0 + r)
                             - 0.01f * i0r;
            step = h * dI;
            x0   = i0r;
        }
    }

    float* __restrict__ row = out + (long long)y * (long long)nt;
    const int t_base = blockIdx.x * EPB;
    // Single int->float conversion; every other index offset is an exact
    // float add (all values < 2^24).
    const float tf_base = (float)(t_base + 4 * (int)threadIdx.x);

    if (t_base + EPB <= nt) {
        // Full tile: 4 batches of 4 front-batched STG.128 each.
        #pragma unroll
        for (int bat = 0; bat < VPT / 4; ++bat) {
            float4 v[4];
            int    off[4];
            #pragma unroll
            for (int j = 0; j < 4; ++j) {
                const int idx = bat * 4 + j;
                off[j] = t_base + (idx * THREADS + threadIdx.x) * 4;
                const float tf = tf_base + (float)(idx * THREADS * 4);
                v[j].x = fmaf(tf,        step, x0);
                v[j].y = fmaf(tf + 1.0f, step, x0);
                v[j].z = fmaf(tf + 2.0f, step, x0);
                v[j].w = fmaf(tf + 3.0f, step, x0);
            }
            #pragma unroll
            for (int j = 0; j < 4; ++j)
                *reinterpret_cast<float4*>(row + off[j]) = v[j];
        }
    } else {
        // Tail tile: per-float4 bounds check, scalar at the very end.
        #pragma unroll
        for (int idx = 0; idx < VPT; ++idx) {
            const int t0 = t_base + (idx * THREADS + threadIdx.x) * 4;
            if (t0 + 3 < nt) {
                const float tf = (float)t0;
                float4 v4;
                v4.x = fmaf(tf,        step, x0);
                v4.y = fmaf(tf + 1.0f, step, x0);
                v4.z = fmaf(tf + 2.0f, step, x0);
                v4.w = fmaf(tf + 3.0f, step, x0);
                *reinterpret_cast<float4*>(row + t0) = v4;
            } else if (t0 < nt) {
                for (int t = t0; t < nt; ++t)
                    row[t] = fmaf((float)t, step, x0);
            }
        }
    }
}

extern "C" void kernel_launch(void* const* d_in, const int* in_sizes, int n_in,
                              void* d_out, int out_size)
{
    const float* S0   = (const float*)d_in[0];
    const float* E0   = (const float*)d_in[1];
    const float* I0   = (const float*)d_in[2];
    const float* L    = (const float*)d_in[3];
    const float* beta = (const float*)d_in[4];
    const float* gam  = (const float*)d_in[5];
    const float* K    = (const float*)d_in[6];
    const float* Ki   = (const float*)d_in[7];
    const float* dt   = (const float*)d_in[8];

    const int nt = out_size / (2 * NROWS);
    float* out = (float*)d_out;

    dim3 grid((nt + EPB - 1) / EPB, 2 * NROWS, 1);
    dim3 block(THREADS, 1, 1);
    sei_fill_kernel<<<grid, block>>>(S0, E0, I0, L, beta, gam, K, Ki, dt, out, nt);
}

// round 16
// speedup vs baseline: 1.1404x; 1.1404x over previous
#include <cuda_runtime.h>
#include <cuda_bf16.h>

// out[m, r, t] = X0[r] + t * fl(dt * dXdt[r]),  m=0 -> S, m=1 -> I
// Closed form matches jax associative_scan cumsum to ~2e-7 (verified R2-R10).
//
// R15 = R14 resubmitted: R14's bench died with cudaErrorSystemNotReady in
// the harness's own init (infra transient on the brokered GB300), never
// reaching kernel code. Kernel unchanged:
//   - R8's proven geometry (VPT=12, 256 thr, grid 41x26=1066, single wave;
//     best measured fill throughput at the ~2.5KB/cyc L2-write ceiling)
//   - float4 X-vector prologue loads (4 LSU entries vs 13)
//   - single I2F per thread; time indices via exact float adds (< 2^24)

#define NROWS 13

static constexpr int THREADS = 256;
static constexpr int VPT     = 12;                  // float4s per thread
static constexpr int EPB     = THREADS * VPT * 4;   // 12288 elems per CTA

__global__ void __launch_bounds__(THREADS)
sei_fill_kernel(const float* __restrict__ S0,
                const float* __restrict__ E0,
                const float* __restrict__ I0,
                const float* __restrict__ L,
                const float* __restrict__ beta_p,
                const float* __restrict__ gamma_p,
                const float* __restrict__ K_p,
                const float* __restrict__ Ki_p,
                const float* __restrict__ dt_p,
                float* __restrict__ out,
                int nt)
{
    const int y = blockIdx.y;                      // row index: m*13 + r
    const int m = (y >= NROWS) ? 1 : 0;
    const int r = y - m * NROWS;

    // Barrier-free prologue: all threads compute the same (step, x0).
    // Uniform loads (warp-broadcast), L1-hit after the first CTAs per SM.
    float step, x0;
    {
        const float* __restrict__ X = (m == 0) ? S0 : I0;

        // X[0..12]: 3x float4 + 1 scalar (4 LSU entries instead of 13).
        float xv[NROWS];
        {
            const float4 a = __ldg((const float4*)(X + 0));
            const float4 b = __ldg((const float4*)(X + 4));
            const float4 c = __ldg((const float4*)(X + 8));
            xv[0]=a.x;  xv[1]=a.y;  xv[2]=a.z;  xv[3]=a.w;
            xv[4]=b.x;  xv[5]=b.y;  xv[6]=b.z;  xv[7]=b.w;
            xv[8]=c.x;  xv[9]=c.y;  xv[10]=c.z; xv[11]=c.w;
            xv[12] = __ldg(X + 12);
        }

        // L row (r*13, unaligned): 13 independent scalar loads, one round.
        float lv[NROWS];
        #pragma unroll
        for (int c = 0; c < NROWS; ++c) lv[c] = __ldg(L + r * NROWS + c);

        float acc = 0.0f;
        #pragma unroll
        for (int c = 0; c < NROWS; ++c) acc = fmaf(lv[c], xv[c], acc);

        const float h   = __ldg(dt_p);
        const float xr  = xv[r];                  // S0[r] or I0[r]
        if (m == 0) {
            const float dS = -__ldg(K_p) * acc
                             - __ldg(beta_p)  * __ldg(E0 + r) * xr
                             - __ldg(gamma_p) * __ldg(I0 + r) * xr;
            step = h * dS;
        } else {
            const float dI = -__ldg(Ki_p) * acc
                             + 0.2f  * __ldg(E0 + r)
                             - 0.01f * xr;
            step = h * dI;
        }
        x0 = xr;
    }

    float* __restrict__ row = out + (long long)y * (long long)nt;
    const int t_base = blockIdx.x * EPB;
    // One I2F per thread; all other time indices are exact float adds
    // (every value < 2^24).
    const float tf_base = (float)(t_base + 4 * (int)threadIdx.x);

    if (t_base + EPB <= nt) {
        // Full tile: 3 batches of 4 front-batched STG.128 each.
        #pragma unroll
        for (int bat = 0; bat < VPT / 4; ++bat) {
            float4 v[4];
            int    off[4];
            #pragma unroll
            for (int j = 0; j < 4; ++j) {
                const int idx = bat * 4 + j;
                off[j] = t_base + (idx * THREADS + threadIdx.x) * 4;
                const float tf = tf_base + (float)(idx * THREADS * 4);
                v[j].x = fmaf(tf,        step, x0);
                v[j].y = fmaf(tf + 1.0f, step, x0);
                v[j].z = fmaf(tf + 2.0f, step, x0);
                v[j].w = fmaf(tf + 3.0f, step, x0);
            }
            #pragma unroll
            for (int j = 0; j < 4; ++j)
                *reinterpret_cast<float4*>(row + off[j]) = v[j];
        }
    } else {
        // Tail tile: per-float4 bounds check, scalar at the very end.
        #pragma unroll
        for (int idx = 0; idx < VPT; ++idx) {
            const int t0 = t_base + (idx * THREADS + threadIdx.x) * 4;
            if (t0 + 3 < nt) {
                const float tf = (float)t0;
                float4 v4;
                v4.x = fmaf(tf,        step, x0);
                v4.y = fmaf(tf + 1.0f, step, x0);
                v4.z = fmaf(tf + 2.0f, step, x0);
                v4.w = fmaf(tf + 3.0f, step, x0);
                *reinterpret_cast<float4*>(row + t0) = v4;
            } else if (t0 < nt) {
                for (int t = t0; t < nt; ++t)
                    row[t] = fmaf((float)t, step, x0);
            }
        }
    }
}

extern "C" void kernel_launch(void* const* d_in, const int* in_sizes, int n_in,
                              void* d_out, int out_size)
{
    const float* S0   = (const float*)d_in[0];
    const float* E0   = (const float*)d_in[1];
    const float* I0   = (const float*)d_in[2];
    const float* L    = (const float*)d_in[3];
    const float* beta = (const float*)d_in[4];
    const float* gam  = (const float*)d_in[5];
    const float* K    = (const float*)d_in[6];
    const float* Ki   = (const float*)d_in[7];
    const float* dt   = (const float*)d_in[8];

    const int nt = out_size / (2 * NROWS);
    float* out = (float*)d_out;

    dim3 grid((nt + EPB - 1) / EPB, 2 * NROWS, 1);
    dim3 block(THREADS, 1, 1);
    sei_fill_kernel<<<grid, block>>>(S0, E0, I0, L, beta, gam, K, Ki, dt, out, nt);
}

// round 17
// speedup vs baseline: 1.1544x; 1.0123x over previous
#include <cuda_runtime.h>
#include <cuda_bf16.h>

// out[m, r, t] = X0[r] + t * fl(dt * dXdt[r]),  m=0 -> S, m=1 -> I
// Closed form matches jax associative_scan cumsum to ~2e-7.
//
// FINAL (= R8, proven 12.768us twice): single kernel node, barrier-free
// per-thread prologue, VPT=12 / 256 thr / grid 41x26=1066 single wave.
// dur_us 12.768 is the steady-state L2-write throughput floor (~4.1 TB/s):
// three structurally different kernels (R2/R4/R8) all measured exactly it,
// and every alternative store path (TMA bulk, fatter CTAs, kernel splits,
// PDL) measured equal or worse (R3/R4/R5/R7/R10/R15).

#define NROWS 13

static constexpr int THREADS = 256;
static constexpr int VPT     = 12;                  // float4s per thread
static constexpr int EPB     = THREADS * VPT * 4;   // 12288 elems per CTA

__global__ void __launch_bounds__(THREADS)
sei_fill_kernel(const float* __restrict__ S0,
                const float* __restrict__ E0,
                const float* __restrict__ I0,
                const float* __restrict__ L,
                const float* __restrict__ beta_p,
                const float* __restrict__ gamma_p,
                const float* __restrict__ K_p,
                const float* __restrict__ Ki_p,
                const float* __restrict__ dt_p,
                float* __restrict__ out,
                int nt)
{
    const int y = blockIdx.y;                      // row index: m*13 + r
    const int m = (y >= NROWS) ? 1 : 0;
    const int r = y - m * NROWS;

    // Barrier-free prologue: all threads compute the same (step, x0).
    // Loads are uniform within the CTA (broadcast); L1-resident after the
    // first CTAs on each SM. The 13-wide dot product uses the idle fma pipe.
    float step, x0;
    {
        const float h = __ldg(dt_p);
        float acc = 0.0f;
        if (m == 0) {
            #pragma unroll
            for (int c = 0; c < NROWS; ++c)
                acc = fmaf(__ldg(L + r * NROWS + c), __ldg(S0 + c), acc);
            const float dS = -__ldg(K_p) * acc
                             - __ldg(beta_p)  * __ldg(E0 + r) * __ldg(S0 + r)
                             - __ldg(gamma_p) * __ldg(I0 + r) * __ldg(S0 + r);
            step = h * dS;
            x0   = __ldg(S0 + r);
        } else {
            #pragma unroll
            for (int c = 0; c < NROWS; ++c)
                acc = fmaf(__ldg(L + r * NROWS + c), __ldg(I0 + c), acc);
            const float dI = -__ldg(Ki_p) * acc
                             + 0.2f  * __ldg(E0 + r)
                             - 0.01f * __ldg(I0 + r);
            step = h * dI;
            x0   = __ldg(I0 + r);
        }
    }

    float* __restrict__ row = out + (long long)y * (long long)nt;
    const int t_base = blockIdx.x * EPB;

    if (t_base + EPB <= nt) {
        // Full tile: 3 batches of 4 front-batched STG.128 each.
        #pragma unroll
        for (int bat = 0; bat < VPT / 4; ++bat) {
            float4 v[4];
            int    off[4];
            #pragma unroll
            for (int j = 0; j < 4; ++j) {
                const int idx = bat * 4 + j;
                const int t0 = t_base + (idx * THREADS + threadIdx.x) * 4;
                off[j] = t0;
                const float tf = (float)t0;
                v[j].x = fmaf(tf,        step, x0);
                v[j].y = fmaf(tf + 1.0f, step, x0);
                v[j].z = fmaf(tf + 2.0f, step, x0);
                v[j].w = fmaf(tf + 3.0f, step, x0);
            }
            #pragma unroll
            for (int j = 0; j < 4; ++j)
                *reinterpret_cast<float4*>(row + off[j]) = v[j];
        }
    } else {
        // Tail tile: per-float4 bounds check, scalar at the very end.
        #pragma unroll
        for (int idx = 0; idx < VPT; ++idx) {
            const int t0 = t_base + (idx * THREADS + threadIdx.x) * 4;
            if (t0 + 3 < nt) {
                const float tf = (float)t0;
                float4 v4;
                v4.x = fmaf(tf,        step, x0);
                v4.y = fmaf(tf + 1.0f, step, x0);
                v4.z = fmaf(tf + 2.0f, step, x0);
                v4.w = fmaf(tf + 3.0f, step, x0);
                *reinterpret_cast<float4*>(row + t0) = v4;
            } else if (t0 < nt) {
                for (int t = t0; t < nt; ++t)
                    row[t] = fmaf((float)t, step, x0);
            }
        }
    }
}

extern "C" void kernel_launch(void* const* d_in, const int* in_sizes, int n_in,
                              void* d_out, int out_size)
{
    const float* S0   = (const float*)d_in[0];
    const float* E0   = (const float*)d_in[1];
    const float* I0   = (const float*)d_in[2];
    const float* L    = (const float*)d_in[3];
    const float* beta = (const float*)d_in[4];
    const float* gam  = (const float*)d_in[5];
    const float* K    = (const float*)d_in[6];
    const float* Ki   = (const float*)d_in[7];
    const float* dt   = (const float*)d_in[8];

    const int nt = out_size / (2 * NROWS);
    float* out = (float*)d_out;

    dim3 grid((nt + EPB - 1) / EPB, 2 * NROWS, 1);
    dim3 block(THREADS, 1, 1);
    sei_fill_kernel<<<grid, block>>>(S0, E0, I0, L, beta, gam, K, Ki, dt, out, nt);
}